// round 1
// baseline (speedup 1.0000x reference)
#include <cuda_runtime.h>

// Problem constants
#define TOK   16384      // tokens per MHA stage (32*512 == 512*32)
#define CDIM  256
#define NHEAD 8
#define DHEAD 32
#define B1    512        // long-attn batch
#define L1    32         // long-attn seq
#define B2    32         // short-attn batch
#define L2    512        // short-attn seq
#define SCALE 0.17677669529663687f  // 1/sqrt(32)

// Scratch (static device globals — allocation-free per harness rules)
__device__ float g_x0[TOK * CDIM];
__device__ float g_x1[TOK * CDIM];
__device__ float g_x2[TOK * CDIM];
__device__ float g_p [TOK * CDIM];
__device__ float g_qb[TOK * CDIM];
__device__ float g_kb[TOK * CDIM];
__device__ float g_vb[TOK * CDIM];
__device__ float g_ob[TOK * CDIM];
__device__ float g_mb[TOK * CDIM];

// ---------------------------------------------------------------------------
// Gather: [n,c,t,h,w] -> long token layout [token= l*512+b, c]
//   l = t*16 + bh*4 + bw ; b = nn*256 + ih*16 + iw ; y = bh*16+ih ; x = bw*16+iw
// Writes: g_x0 = q+pos, g_x1 = k+pos, g_x2 = v, g_p = pos
// grid (16, 64, 4)  block (32, 8)
// ---------------------------------------------------------------------------
__global__ void gather_long(const float* __restrict__ q, const float* __restrict__ k,
                            const float* __restrict__ v, const float* __restrict__ p) {
    int ct = blockIdx.x >> 1, xt = blockIdx.x & 1;
    int y  = blockIdx.y;
    int nn = blockIdx.z >> 1, t = blockIdx.z & 1;
    int c0 = ct * 32, x0 = xt * 32;
    __shared__ float sq[32][33], sk[32][33], sv[32][33], sp[32][33];
    int tx = threadIdx.x, ty = threadIdx.y;
    #pragma unroll
    for (int i = 0; i < 4; i++) {
        int ci = ty + i * 8;
        size_t idx = ((size_t)(nn * CDIM + c0 + ci) * 2 + t) * 4096 + (size_t)y * 64 + x0 + tx;
        float pv = p[idx];
        sq[ci][tx] = q[idx] + pv;
        sk[ci][tx] = k[idx] + pv;
        sv[ci][tx] = v[idx];
        sp[ci][tx] = pv;
    }
    __syncthreads();
    int bh = y >> 4, ih = y & 15;
    #pragma unroll
    for (int i = 0; i < 4; i++) {
        int xi = ty + i * 8;
        int x = x0 + xi;
        int bw = x >> 4, iw = x & 15;
        int token = (t * 16 + bh * 4 + bw) * 512 + nn * 256 + ih * 16 + iw;
        size_t o = (size_t)token * CDIM + c0 + tx;
        g_x0[o] = sq[tx][xi];
        g_x1[o] = sk[tx][xi];
        g_x2[o] = sv[tx][xi];
        g_p [o] = sp[tx][xi];
    }
}

// ---------------------------------------------------------------------------
// GEMM: Y[M,256] = X[M,256] @ W[256(n),256(k)]^T + bias     (M = 16384)
// Tiles: BM=128, BN=64, BK=16 ; 256 threads ; 8x4 register tile per thread
// grid (4, 128) block (256)
// ---------------------------------------------------------------------------
__global__ __launch_bounds__(256) void gemm_nt(const float* __restrict__ X,
                                               const float* __restrict__ Wm,
                                               const float* __restrict__ bias,
                                               float* __restrict__ Y) {
    __shared__ float As[16][128];
    __shared__ float Bs[16][64];
    int tid = threadIdx.x;
    int n0 = blockIdx.x * 64;
    int m0 = blockIdx.y * 128;
    int tm = tid >> 4, tn = tid & 15;

    float acc[8][4];
    #pragma unroll
    for (int r = 0; r < 8; r++)
        #pragma unroll
        for (int c = 0; c < 4; c++) acc[r][c] = 0.f;

    int ar0 = tid >> 2;        // 0..63
    int ar1 = 64 + ar0;        // 64..127
    int ac4 = tid & 3;
    int br  = tid >> 2;        // 0..63
    int bc4 = tid & 3;

    const float4* X4 = (const float4*)X;
    const float4* W4 = (const float4*)Wm;

    for (int kt = 0; kt < 16; kt++) {
        float4 a0 = X4[(size_t)(m0 + ar0) * 64 + kt * 4 + ac4];
        float4 a1 = X4[(size_t)(m0 + ar1) * 64 + kt * 4 + ac4];
        float4 b0 = W4[(size_t)(n0 + br) * 64 + kt * 4 + bc4];
        __syncthreads();
        As[ac4 * 4 + 0][ar0] = a0.x; As[ac4 * 4 + 1][ar0] = a0.y;
        As[ac4 * 4 + 2][ar0] = a0.z; As[ac4 * 4 + 3][ar0] = a0.w;
        As[ac4 * 4 + 0][ar1] = a1.x; As[ac4 * 4 + 1][ar1] = a1.y;
        As[ac4 * 4 + 2][ar1] = a1.z; As[ac4 * 4 + 3][ar1] = a1.w;
        Bs[bc4 * 4 + 0][br] = b0.x; Bs[bc4 * 4 + 1][br] = b0.y;
        Bs[bc4 * 4 + 2][br] = b0.z; Bs[bc4 * 4 + 3][br] = b0.w;
        __syncthreads();
        #pragma unroll
        for (int kk = 0; kk < 16; kk++) {
            float4 av0 = *(const float4*)&As[kk][tm * 8];
            float4 av1 = *(const float4*)&As[kk][tm * 8 + 4];
            float4 bv  = *(const float4*)&Bs[kk][tn * 4];
            float a[8] = {av0.x, av0.y, av0.z, av0.w, av1.x, av1.y, av1.z, av1.w};
            float b[4] = {bv.x, bv.y, bv.z, bv.w};
            #pragma unroll
            for (int r = 0; r < 8; r++)
                #pragma unroll
                for (int c = 0; c < 4; c++) acc[r][c] += a[r] * b[c];
        }
    }
    float4 bb = *(const float4*)&bias[n0 + tn * 4];
    #pragma unroll
    for (int r = 0; r < 8; r++) {
        float4 o;
        o.x = acc[r][0] + bb.x; o.y = acc[r][1] + bb.y;
        o.z = acc[r][2] + bb.z; o.w = acc[r][3] + bb.w;
        *(float4*)&Y[(size_t)(m0 + tm * 8 + r) * CDIM + n0 + tn * 4] = o;
    }
}

// ---------------------------------------------------------------------------
// Attention #1 (long): Lq=Lk=32, d=32; one warp per (b,h); thread = query row.
// Layout: elem (l, dd) of (b,h) at l*131072 + b*256 + h*32 + dd
// grid (512, 8) block (32)
// ---------------------------------------------------------------------------
__global__ void attn1(const float* __restrict__ Q, const float* __restrict__ K,
                      const float* __restrict__ V, float* __restrict__ O) {
    int b = blockIdx.x, h = blockIdx.y;
    size_t base = (size_t)b * CDIM + h * DHEAD;
    __shared__ float Ks[32][36], Vs[32][36];
    int tid = threadIdx.x;
    for (int r = 0; r < 32; r++) {
        size_t idx = (size_t)r * 131072 + base + tid;
        Ks[r][tid] = K[idx];
        Vs[r][tid] = V[idx];
    }
    __syncthreads();
    float q[32];
    const float4* q4 = (const float4*)(Q + (size_t)tid * 131072 + base);
    #pragma unroll
    for (int d4 = 0; d4 < 8; d4++) {
        float4 qq = q4[d4];
        q[d4 * 4 + 0] = qq.x * SCALE; q[d4 * 4 + 1] = qq.y * SCALE;
        q[d4 * 4 + 2] = qq.z * SCALE; q[d4 * 4 + 3] = qq.w * SCALE;
    }
    float s[32];
    float m = -1e30f;
    #pragma unroll
    for (int j = 0; j < 32; j++) {
        const float4* kr = (const float4*)Ks[j];
        float a = 0.f;
        #pragma unroll
        for (int d4 = 0; d4 < 8; d4++) {
            float4 kv = kr[d4];
            a += q[d4 * 4 + 0] * kv.x + q[d4 * 4 + 1] * kv.y
               + q[d4 * 4 + 2] * kv.z + q[d4 * 4 + 3] * kv.w;
        }
        s[j] = a;
        m = fmaxf(m, a);
    }
    float lsum = 0.f;
    #pragma unroll
    for (int j = 0; j < 32; j++) { s[j] = __expf(s[j] - m); lsum += s[j]; }
    float acc[32];
    #pragma unroll
    for (int d = 0; d < 32; d++) acc[d] = 0.f;
    #pragma unroll
    for (int j = 0; j < 32; j++) {
        const float4* vr = (const float4*)Vs[j];
        float pj = s[j];
        #pragma unroll
        for (int d4 = 0; d4 < 8; d4++) {
            float4 vv = vr[d4];
            acc[d4 * 4 + 0] += pj * vv.x; acc[d4 * 4 + 1] += pj * vv.y;
            acc[d4 * 4 + 2] += pj * vv.z; acc[d4 * 4 + 3] += pj * vv.w;
        }
    }
    float inv = 1.f / lsum;
    float4* o4 = (float4*)(O + (size_t)tid * 131072 + base);
    #pragma unroll
    for (int d4 = 0; d4 < 8; d4++) {
        float4 oo;
        oo.x = acc[d4 * 4 + 0] * inv; oo.y = acc[d4 * 4 + 1] * inv;
        oo.z = acc[d4 * 4 + 2] * inv; oo.w = acc[d4 * 4 + 3] * inv;
        o4[d4] = oo;
    }
}

// ---------------------------------------------------------------------------
// Re-index long -> short, add pos: g_x0 = v1[perm]+pos, g_x2 = v1[perm]
// token2 = s*32+b2 ; s=(t,ih,iw) ; b2=(nn,bh,bw) ; long token = l*512+b
// grid (16384) block (256)
// ---------------------------------------------------------------------------
__global__ void reindex_short() {
    int token2 = blockIdx.x;
    int s = token2 >> 5, b2 = token2 & 31;
    int t = s >> 8, rem = s & 255, ih = rem >> 4, iw = rem & 15;
    int nn = b2 >> 4, rr = b2 & 15, bh = rr >> 2, bw = rr & 3;
    int token = (t * 16 + bh * 4 + bw) * 512 + nn * 256 + ih * 16 + iw;
    int c = threadIdx.x;
    size_t si = (size_t)token * CDIM + c;
    size_t di = (size_t)token2 * CDIM + c;
    float x = g_mb[si];
    float pp = g_p[si];
    g_x0[di] = x + pp;
    g_x2[di] = x;
}

// ---------------------------------------------------------------------------
// Attention #2 (short): L=512, d=32; flash-style, thread = query row.
// Layout: elem (l, dd) of (b2,h) at l*8192 + b2*256 + h*32 + dd
// grid (4, 8, 32) block (128)  — 128 queries per block, key tiles of 64
// ---------------------------------------------------------------------------
__global__ __launch_bounds__(128) void attn2(const float* __restrict__ Q,
                                             const float* __restrict__ K,
                                             const float* __restrict__ V,
                                             float* __restrict__ O) {
    int qt = blockIdx.x, h = blockIdx.y, b2 = blockIdx.z;
    size_t base = (size_t)b2 * CDIM + h * DHEAD;
    int tid = threadIdx.x;
    int l = qt * 128 + tid;
    __shared__ float Ks[64][36], Vs[64][36];

    float q[32], acc[32];
    const float4* q4 = (const float4*)(Q + (size_t)l * 8192 + base);
    #pragma unroll
    for (int d4 = 0; d4 < 8; d4++) {
        float4 qq = q4[d4];
        q[d4 * 4 + 0] = qq.x * SCALE; q[d4 * 4 + 1] = qq.y * SCALE;
        q[d4 * 4 + 2] = qq.z * SCALE; q[d4 * 4 + 3] = qq.w * SCALE;
    }
    #pragma unroll
    for (int d = 0; d < 32; d++) acc[d] = 0.f;
    float m = -1e30f, lsum = 0.f;

    for (int kt = 0; kt < 8; kt++) {
        int k0 = kt * 64;
        __syncthreads();
        #pragma unroll
        for (int i = 0; i < 16; i++) {
            int r = (tid >> 5) + i * 4;
            int col = tid & 31;
            size_t idx = (size_t)(k0 + r) * 8192 + base + col;
            Ks[r][col] = K[idx];
            Vs[r][col] = V[idx];
        }
        __syncthreads();
        float s[64];
        float mt = -1e30f;
        #pragma unroll
        for (int j = 0; j < 64; j++) {
            const float4* kr = (const float4*)Ks[j];
            float a = 0.f;
            #pragma unroll
            for (int d4 = 0; d4 < 8; d4++) {
                float4 kv = kr[d4];
                a += q[d4 * 4 + 0] * kv.x + q[d4 * 4 + 1] * kv.y
                   + q[d4 * 4 + 2] * kv.z + q[d4 * 4 + 3] * kv.w;
            }
            s[j] = a;
            mt = fmaxf(mt, a);
        }
        float mnew = fmaxf(m, mt);
        float corr = __expf(m - mnew);
        lsum *= corr;
        #pragma unroll
        for (int d = 0; d < 32; d++) acc[d] *= corr;
        #pragma unroll
        for (int j = 0; j < 64; j++) {
            float pj = __expf(s[j] - mnew);
            lsum += pj;
            s[j] = pj;
        }
        #pragma unroll
        for (int j = 0; j < 64; j++) {
            const float4* vr = (const float4*)Vs[j];
            float pj = s[j];
            #pragma unroll
            for (int d4 = 0; d4 < 8; d4++) {
                float4 vv = vr[d4];
                acc[d4 * 4 + 0] += pj * vv.x; acc[d4 * 4 + 1] += pj * vv.y;
                acc[d4 * 4 + 2] += pj * vv.z; acc[d4 * 4 + 3] += pj * vv.w;
            }
        }
        m = mnew;
    }
    float inv = 1.f / lsum;
    float4* o4 = (float4*)(O + (size_t)l * 8192 + base);
    #pragma unroll
    for (int d4 = 0; d4 < 8; d4++) {
        float4 oo;
        oo.x = acc[d4 * 4 + 0] * inv; oo.y = acc[d4 * 4 + 1] * inv;
        oo.z = acc[d4 * 4 + 2] * inv; oo.w = acc[d4 * 4 + 3] * inv;
        o4[d4] = oo;
    }
}

// ---------------------------------------------------------------------------
// Scatter: short token layout -> output [n,c,t,h,w]
// grid (16, 64, 4) block (32, 8)
// ---------------------------------------------------------------------------
__global__ void scatter_out(const float* __restrict__ src, float* __restrict__ out) {
    int ct = blockIdx.x >> 1, xt = blockIdx.x & 1;
    int y  = blockIdx.y;
    int nn = blockIdx.z >> 1, t = blockIdx.z & 1;
    int c0 = ct * 32, x0 = xt * 32;
    int bh = y >> 4, ih = y & 15;
    __shared__ float sm[32][33];
    int tx = threadIdx.x, ty = threadIdx.y;
    #pragma unroll
    for (int i = 0; i < 4; i++) {
        int xi = ty + i * 8;
        int x = x0 + xi;
        int bw = x >> 4, iw = x & 15;
        int s  = t * 256 + ih * 16 + iw;
        int b2 = nn * 16 + bh * 4 + bw;
        int token2 = s * 32 + b2;
        sm[tx][xi] = src[(size_t)token2 * CDIM + c0 + tx];
    }
    __syncthreads();
    #pragma unroll
    for (int i = 0; i < 4; i++) {
        int ci = ty + i * 8;
        out[((size_t)(nn * CDIM + c0 + ci) * 2 + t) * 4096 + (size_t)y * 64 + x0 + tx] = sm[ci][tx];
    }
}

// ---------------------------------------------------------------------------
extern "C" void kernel_launch(void* const* d_in, const int* in_sizes, int n_in,
                              void* d_out, int out_size) {
    (void)in_sizes; (void)n_in; (void)out_size;
    const float* q      = (const float*)d_in[0];
    const float* k      = (const float*)d_in[1];
    const float* v      = (const float*)d_in[2];
    const float* pos    = (const float*)d_in[3];
    const float* wl_in  = (const float*)d_in[4];
    const float* bl_in  = (const float*)d_in[5];
    const float* wl_out = (const float*)d_in[6];
    const float* bl_out = (const float*)d_in[7];
    const float* ws_in  = (const float*)d_in[8];
    const float* bs_in  = (const float*)d_in[9];
    const float* ws_out = (const float*)d_in[10];
    const float* bs_out = (const float*)d_in[11];
    float* out = (float*)d_out;

    float *px0, *px1, *px2, *pq, *pk, *pv, *po, *pm;
    cudaGetSymbolAddress((void**)&px0, g_x0);
    cudaGetSymbolAddress((void**)&px1, g_x1);
    cudaGetSymbolAddress((void**)&px2, g_x2);
    cudaGetSymbolAddress((void**)&pq,  g_qb);
    cudaGetSymbolAddress((void**)&pk,  g_kb);
    cudaGetSymbolAddress((void**)&pv,  g_vb);
    cudaGetSymbolAddress((void**)&po,  g_ob);
    cudaGetSymbolAddress((void**)&pm,  g_mb);

    dim3 gGather(16, 64, 4), bGather(32, 8);
    dim3 gGemm(4, 128);
    dim3 gAttn1(512, 8);
    dim3 gAttn2(4, 8, 32);

    // Phase 1: gather to long layout (+pos)
    gather_long<<<gGather, bGather>>>(q, k, v, pos);

    // Phase 2: MHA1 input projections
    gemm_nt<<<gGemm, 256>>>(px0, wl_in,              bl_in,       pq);
    gemm_nt<<<gGemm, 256>>>(px1, wl_in + 256 * 256,  bl_in + 256, pk);
    gemm_nt<<<gGemm, 256>>>(px2, wl_in + 512 * 256,  bl_in + 512, pv);

    // Phase 3: long attention
    attn1<<<gAttn1, 32>>>(pq, pk, pv, po);

    // Phase 4: MHA1 output projection
    gemm_nt<<<gGemm, 256>>>(po, wl_out, bl_out, pm);

    // Phase 5: permute long -> short, add pos
    reindex_short<<<TOK, 256>>>();

    // Phase 6: MHA2 input projections (query and key share input g_x0)
    gemm_nt<<<gGemm, 256>>>(px0, ws_in,              bs_in,       pq);
    gemm_nt<<<gGemm, 256>>>(px0, ws_in + 256 * 256,  bs_in + 256, pk);
    gemm_nt<<<gGemm, 256>>>(px2, ws_in + 512 * 256,  bs_in + 512, pv);

    // Phase 7: short attention (flash)
    attn2<<<gAttn2, 128>>>(pq, pk, pv, po);

    // Phase 8: MHA2 output projection + scatter to output layout
    gemm_nt<<<gGemm, 256>>>(po, ws_out, bs_out, pm);
    scatter_out<<<gGather, bGather>>>(pm, out);
}

// round 3
// speedup vs baseline: 1.2856x; 1.2856x over previous
#include <cuda_runtime.h>
#include <cuda_bf16.h>
#include <cstdint>

// Problem constants
#define TOK   16384      // tokens per MHA stage (32*512 == 512*32)
#define CDIM  256
#define NHEAD 8
#define DHEAD 32
#define SCALE 0.17677669529663687f  // 1/sqrt(32)

// Scratch (static device globals — allocation-free per harness rules)
__device__ float g_x0[TOK * CDIM];
__device__ float g_x1[TOK * CDIM];
__device__ float g_x2[TOK * CDIM];
__device__ float g_p [TOK * CDIM];
__device__ float g_qb[TOK * CDIM];
__device__ float g_kb[TOK * CDIM];
__device__ float g_vb[TOK * CDIM];
__device__ float g_ob[TOK * CDIM];
__device__ float g_mb[TOK * CDIM];

// ---------------------------------------------------------------------------
// Gather: [n,c,t,h,w] -> long token layout [token= l*512+b, c]
// ---------------------------------------------------------------------------
__global__ void gather_long(const float* __restrict__ q, const float* __restrict__ k,
                            const float* __restrict__ v, const float* __restrict__ p) {
    int ct = blockIdx.x >> 1, xt = blockIdx.x & 1;
    int y  = blockIdx.y;
    int nn = blockIdx.z >> 1, t = blockIdx.z & 1;
    int c0 = ct * 32, x0 = xt * 32;
    __shared__ float sq[32][33], sk[32][33], sv[32][33], sp[32][33];
    int tx = threadIdx.x, ty = threadIdx.y;
    #pragma unroll
    for (int i = 0; i < 4; i++) {
        int ci = ty + i * 8;
        size_t idx = ((size_t)(nn * CDIM + c0 + ci) * 2 + t) * 4096 + (size_t)y * 64 + x0 + tx;
        float pv = p[idx];
        sq[ci][tx] = q[idx] + pv;
        sk[ci][tx] = k[idx] + pv;
        sv[ci][tx] = v[idx];
        sp[ci][tx] = pv;
    }
    __syncthreads();
    int bh = y >> 4, ih = y & 15;
    #pragma unroll
    for (int i = 0; i < 4; i++) {
        int xi = ty + i * 8;
        int x = x0 + xi;
        int bw = x >> 4, iw = x & 15;
        int token = (t * 16 + bh * 4 + bw) * 512 + nn * 256 + ih * 16 + iw;
        size_t o = (size_t)token * CDIM + c0 + tx;
        g_x0[o] = sq[tx][xi];
        g_x1[o] = sk[tx][xi];
        g_x2[o] = sv[tx][xi];
        g_p [o] = sp[tx][xi];
    }
}

// ---------------------------------------------------------------------------
// Tensor-core GEMM with bf16 split (hi/lo): Y[M,256] = X[M,256] @ W^T + bias
// BM=128, BN=64, BK=32; 256 threads = 8 warps (4m x 2n); warp tile 32x32.
// Each fp32 input is split: hi = bf16(x), lo = bf16(x - hi); three MMA terms
// hi*hi + hi*lo + lo*hi give ~1e-5 relative accuracy with fp32 accumulators.
// grid (4, 128)  block (256)
// ---------------------------------------------------------------------------
#define LDSR 40   // padded smem row stride in bf16 elements (80B: conflict-free)

__device__ __forceinline__ void mma_bf16(float* d, const uint32_t* a, const uint32_t* b) {
    asm volatile(
        "mma.sync.aligned.m16n8k16.row.col.f32.bf16.bf16.f32 "
        "{%0,%1,%2,%3}, {%4,%5,%6,%7}, {%8,%9}, {%0,%1,%2,%3};"
        : "+f"(d[0]), "+f"(d[1]), "+f"(d[2]), "+f"(d[3])
        : "r"(a[0]), "r"(a[1]), "r"(a[2]), "r"(a[3]), "r"(b[0]), "r"(b[1]));
}

__device__ __forceinline__ void ldsm_x4(uint32_t* r, const __nv_bfloat16* p) {
    uint32_t addr = (uint32_t)__cvta_generic_to_shared(p);
    asm volatile("ldmatrix.sync.aligned.m8n8.x4.shared.b16 {%0,%1,%2,%3}, [%4];"
                 : "=r"(r[0]), "=r"(r[1]), "=r"(r[2]), "=r"(r[3]) : "r"(addr));
}

__device__ __forceinline__ void ldsm_x2(uint32_t* r, const __nv_bfloat16* p) {
    uint32_t addr = (uint32_t)__cvta_generic_to_shared(p);
    asm volatile("ldmatrix.sync.aligned.m8n8.x2.shared.b16 {%0,%1}, [%2];"
                 : "=r"(r[0]), "=r"(r[1]) : "r"(addr));
}

__device__ __forceinline__ void split_store(__nv_bfloat16* hi, __nv_bfloat16* lo, float v) {
    __nv_bfloat16 h = __float2bfloat16(v);
    *hi = h;
    *lo = __float2bfloat16(v - __bfloat162float(h));
}

__global__ __launch_bounds__(256) void gemm_nt_tc(const float* __restrict__ X,
                                                  const float* __restrict__ Wm,
                                                  const float* __restrict__ bias,
                                                  float* __restrict__ Y) {
    __shared__ __nv_bfloat16 As_hi[128 * LDSR], As_lo[128 * LDSR];
    __shared__ __nv_bfloat16 Bs_hi[64 * LDSR],  Bs_lo[64 * LDSR];

    int tid  = threadIdx.x;
    int warp = tid >> 5, lane = tid & 31;
    int m0 = blockIdx.y * 128, n0 = blockIdx.x * 64;
    int wm = (warp >> 1) * 32;     // 4 warps over m
    int wn = (warp & 1) * 32;      // 2 warps over n

    float acc[2][4][4];
    #pragma unroll
    for (int mi = 0; mi < 2; mi++)
        #pragma unroll
        for (int ni = 0; ni < 4; ni++)
            #pragma unroll
            for (int e = 0; e < 4; e++) acc[mi][ni][e] = 0.f;

    const float4* X4 = (const float4*)X;
    const float4* W4 = (const float4*)Wm;
    int lrow  = tid >> 3;   // 0..31
    int lcol4 = tid & 7;    // 0..7 float4 column within 32-wide K tile

    // ldmatrix source pointers (fixed per thread, per kk-half offset applied later)
    int al16 = lane & 15;
    const __nv_bfloat16* pa_hi0 = &As_hi[(wm + al16) * LDSR + (lane >> 4) * 8];
    const __nv_bfloat16* pa_lo0 = &As_lo[(wm + al16) * LDSR + (lane >> 4) * 8];
    const __nv_bfloat16* pb_hi0 = &Bs_hi[(wn + (al16 & 7)) * LDSR + (al16 >> 3) * 8];
    const __nv_bfloat16* pb_lo0 = &Bs_lo[(wn + (al16 & 7)) * LDSR + (al16 >> 3) * 8];

    for (int kt = 0; kt < 8; kt++) {
        __syncthreads();
        // Stage X tile [128 x 32] fp32 -> bf16 hi/lo
        #pragma unroll
        for (int i = 0; i < 4; i++) {
            int r = lrow + i * 32;
            float4 xv = X4[(size_t)(m0 + r) * 64 + kt * 8 + lcol4];
            __nv_bfloat16* h = &As_hi[r * LDSR + lcol4 * 4];
            __nv_bfloat16* l = &As_lo[r * LDSR + lcol4 * 4];
            split_store(h + 0, l + 0, xv.x);
            split_store(h + 1, l + 1, xv.y);
            split_store(h + 2, l + 2, xv.z);
            split_store(h + 3, l + 3, xv.w);
        }
        // Stage W tile [64 x 32]
        #pragma unroll
        for (int i = 0; i < 2; i++) {
            int r = lrow + i * 32;
            float4 wv = W4[(size_t)(n0 + r) * 64 + kt * 8 + lcol4];
            __nv_bfloat16* h = &Bs_hi[r * LDSR + lcol4 * 4];
            __nv_bfloat16* l = &Bs_lo[r * LDSR + lcol4 * 4];
            split_store(h + 0, l + 0, wv.x);
            split_store(h + 1, l + 1, wv.y);
            split_store(h + 2, l + 2, wv.z);
            split_store(h + 3, l + 3, wv.w);
        }
        __syncthreads();

        #pragma unroll
        for (int kk = 0; kk < 2; kk++) {
            int ko = kk * 16;
            uint32_t ah[2][4], al[2][4];
            #pragma unroll
            for (int mi = 0; mi < 2; mi++) {
                ldsm_x4(ah[mi], pa_hi0 + mi * 16 * LDSR + ko);
                ldsm_x4(al[mi], pa_lo0 + mi * 16 * LDSR + ko);
            }
            uint32_t bh[4][2], bl[4][2];
            #pragma unroll
            for (int ni = 0; ni < 4; ni++) {
                ldsm_x2(bh[ni], pb_hi0 + ni * 8 * LDSR + ko);
                ldsm_x2(bl[ni], pb_lo0 + ni * 8 * LDSR + ko);
            }
            #pragma unroll
            for (int mi = 0; mi < 2; mi++)
                #pragma unroll
                for (int ni = 0; ni < 4; ni++) {
                    mma_bf16(acc[mi][ni], ah[mi], bh[ni]);
                    mma_bf16(acc[mi][ni], ah[mi], bl[ni]);
                    mma_bf16(acc[mi][ni], al[mi], bh[ni]);
                }
        }
    }

    // Epilogue: C fragment m16n8 layout -> Y, with bias
    int cr = lane >> 2;           // 0..7
    int cc = (lane & 3) * 2;      // 0,2,4,6
    #pragma unroll
    for (int mi = 0; mi < 2; mi++) {
        #pragma unroll
        for (int ni = 0; ni < 4; ni++) {
            int col = n0 + wn + ni * 8 + cc;
            float b0 = bias[col], b1 = bias[col + 1];
            int row0 = m0 + wm + mi * 16 + cr;
            float2 o0 = make_float2(acc[mi][ni][0] + b0, acc[mi][ni][1] + b1);
            float2 o1 = make_float2(acc[mi][ni][2] + b0, acc[mi][ni][3] + b1);
            *(float2*)&Y[(size_t)row0 * CDIM + col]       = o0;
            *(float2*)&Y[(size_t)(row0 + 8) * CDIM + col] = o1;
        }
    }
}

// ---------------------------------------------------------------------------
// Attention #1 (long): Lq=Lk=32, d=32; one warp per (b,h); thread = query row.
// grid (512, 8) block (32)
// ---------------------------------------------------------------------------
__global__ void attn1(const float* __restrict__ Q, const float* __restrict__ K,
                      const float* __restrict__ V, float* __restrict__ O) {
    int b = blockIdx.x, h = blockIdx.y;
    size_t base = (size_t)b * CDIM + h * DHEAD;
    __shared__ float Ks[32][36], Vs[32][36];
    int tid = threadIdx.x;
    for (int r = 0; r < 32; r++) {
        size_t idx = (size_t)r * 131072 + base + tid;
        Ks[r][tid] = K[idx];
        Vs[r][tid] = V[idx];
    }
    __syncthreads();
    float q[32];
    const float4* q4 = (const float4*)(Q + (size_t)tid * 131072 + base);
    #pragma unroll
    for (int d4 = 0; d4 < 8; d4++) {
        float4 qq = q4[d4];
        q[d4 * 4 + 0] = qq.x * SCALE; q[d4 * 4 + 1] = qq.y * SCALE;
        q[d4 * 4 + 2] = qq.z * SCALE; q[d4 * 4 + 3] = qq.w * SCALE;
    }
    float s[32];
    float m = -1e30f;
    #pragma unroll
    for (int j = 0; j < 32; j++) {
        const float4* kr = (const float4*)Ks[j];
        float a = 0.f;
        #pragma unroll
        for (int d4 = 0; d4 < 8; d4++) {
            float4 kv = kr[d4];
            a += q[d4 * 4 + 0] * kv.x + q[d4 * 4 + 1] * kv.y
               + q[d4 * 4 + 2] * kv.z + q[d4 * 4 + 3] * kv.w;
        }
        s[j] = a;
        m = fmaxf(m, a);
    }
    float lsum = 0.f;
    #pragma unroll
    for (int j = 0; j < 32; j++) { s[j] = __expf(s[j] - m); lsum += s[j]; }
    float acc[32];
    #pragma unroll
    for (int d = 0; d < 32; d++) acc[d] = 0.f;
    #pragma unroll
    for (int j = 0; j < 32; j++) {
        const float4* vr = (const float4*)Vs[j];
        float pj = s[j];
        #pragma unroll
        for (int d4 = 0; d4 < 8; d4++) {
            float4 vv = vr[d4];
            acc[d4 * 4 + 0] += pj * vv.x; acc[d4 * 4 + 1] += pj * vv.y;
            acc[d4 * 4 + 2] += pj * vv.z; acc[d4 * 4 + 3] += pj * vv.w;
        }
    }
    float inv = 1.f / lsum;
    float4* o4 = (float4*)(O + (size_t)tid * 131072 + base);
    #pragma unroll
    for (int d4 = 0; d4 < 8; d4++) {
        float4 oo;
        oo.x = acc[d4 * 4 + 0] * inv; oo.y = acc[d4 * 4 + 1] * inv;
        oo.z = acc[d4 * 4 + 2] * inv; oo.w = acc[d4 * 4 + 3] * inv;
        o4[d4] = oo;
    }
}

// ---------------------------------------------------------------------------
// Re-index long -> short, add pos
// grid (16384) block (256)
// ---------------------------------------------------------------------------
__global__ void reindex_short() {
    int token2 = blockIdx.x;
    int s = token2 >> 5, b2 = token2 & 31;
    int t = s >> 8, rem = s & 255, ih = rem >> 4, iw = rem & 15;
    int nn = b2 >> 4, rr = b2 & 15, bh = rr >> 2, bw = rr & 3;
    int token = (t * 16 + bh * 4 + bw) * 512 + nn * 256 + ih * 16 + iw;
    int c = threadIdx.x;
    size_t si = (size_t)token * CDIM + c;
    size_t di = (size_t)token2 * CDIM + c;
    float x = g_mb[si];
    float pp = g_p[si];
    g_x0[di] = x + pp;
    g_x2[di] = x;
}

// ---------------------------------------------------------------------------
// Attention #2 (short): L=512, d=32; flash-style, thread = query row.
// grid (4, 8, 32) block (128)
// ---------------------------------------------------------------------------
__global__ __launch_bounds__(128) void attn2(const float* __restrict__ Q,
                                             const float* __restrict__ K,
                                             const float* __restrict__ V,
                                             float* __restrict__ O) {
    int qt = blockIdx.x, h = blockIdx.y, b2 = blockIdx.z;
    size_t base = (size_t)b2 * CDIM + h * DHEAD;
    int tid = threadIdx.x;
    int l = qt * 128 + tid;
    __shared__ float Ks[64][36], Vs[64][36];

    float q[32], acc[32];
    const float4* q4 = (const float4*)(Q + (size_t)l * 8192 + base);
    #pragma unroll
    for (int d4 = 0; d4 < 8; d4++) {
        float4 qq = q4[d4];
        q[d4 * 4 + 0] = qq.x * SCALE; q[d4 * 4 + 1] = qq.y * SCALE;
        q[d4 * 4 + 2] = qq.z * SCALE; q[d4 * 4 + 3] = qq.w * SCALE;
    }
    #pragma unroll
    for (int d = 0; d < 32; d++) acc[d] = 0.f;
    float m = -1e30f, lsum = 0.f;

    for (int kt = 0; kt < 8; kt++) {
        int k0 = kt * 64;
        __syncthreads();
        #pragma unroll
        for (int i = 0; i < 16; i++) {
            int r = (tid >> 5) + i * 4;
            int col = tid & 31;
            size_t idx = (size_t)(k0 + r) * 8192 + base + col;
            Ks[r][col] = K[idx];
            Vs[r][col] = V[idx];
        }
        __syncthreads();
        float s[64];
        float mt = -1e30f;
        #pragma unroll
        for (int j = 0; j < 64; j++) {
            const float4* kr = (const float4*)Ks[j];
            float a = 0.f;
            #pragma unroll
            for (int d4 = 0; d4 < 8; d4++) {
                float4 kv = kr[d4];
                a += q[d4 * 4 + 0] * kv.x + q[d4 * 4 + 1] * kv.y
                   + q[d4 * 4 + 2] * kv.z + q[d4 * 4 + 3] * kv.w;
            }
            s[j] = a;
            mt = fmaxf(mt, a);
        }
        float mnew = fmaxf(m, mt);
        float corr = __expf(m - mnew);
        lsum *= corr;
        #pragma unroll
        for (int d = 0; d < 32; d++) acc[d] *= corr;
        #pragma unroll
        for (int j = 0; j < 64; j++) {
            float pj = __expf(s[j] - mnew);
            lsum += pj;
            s[j] = pj;
        }
        #pragma unroll
        for (int j = 0; j < 64; j++) {
            const float4* vr = (const float4*)Vs[j];
            float pj = s[j];
            #pragma unroll
            for (int d4 = 0; d4 < 8; d4++) {
                float4 vv = vr[d4];
                acc[d4 * 4 + 0] += pj * vv.x; acc[d4 * 4 + 1] += pj * vv.y;
                acc[d4 * 4 + 2] += pj * vv.z; acc[d4 * 4 + 3] += pj * vv.w;
            }
        }
        m = mnew;
    }
    float inv = 1.f / lsum;
    float4* o4 = (float4*)(O + (size_t)l * 8192 + base);
    #pragma unroll
    for (int d4 = 0; d4 < 8; d4++) {
        float4 oo;
        oo.x = acc[d4 * 4 + 0] * inv; oo.y = acc[d4 * 4 + 1] * inv;
        oo.z = acc[d4 * 4 + 2] * inv; oo.w = acc[d4 * 4 + 3] * inv;
        o4[d4] = oo;
    }
}

// ---------------------------------------------------------------------------
// Scatter: short token layout -> output [n,c,t,h,w]
// grid (16, 64, 4) block (32, 8)
// ---------------------------------------------------------------------------
__global__ void scatter_out(const float* __restrict__ src, float* __restrict__ out) {
    int ct = blockIdx.x >> 1, xt = blockIdx.x & 1;
    int y  = blockIdx.y;
    int nn = blockIdx.z >> 1, t = blockIdx.z & 1;
    int c0 = ct * 32, x0 = xt * 32;
    int bh = y >> 4, ih = y & 15;
    __shared__ float sm[32][33];
    int tx = threadIdx.x, ty = threadIdx.y;
    #pragma unroll
    for (int i = 0; i < 4; i++) {
        int xi = ty + i * 8;
        int x = x0 + xi;
        int bw = x >> 4, iw = x & 15;
        int s  = t * 256 + ih * 16 + iw;
        int b2 = nn * 16 + bh * 4 + bw;
        int token2 = s * 32 + b2;
        sm[tx][xi] = src[(size_t)token2 * CDIM + c0 + tx];
    }
    __syncthreads();
    #pragma unroll
    for (int i = 0; i < 4; i++) {
        int ci = ty + i * 8;
        out[((size_t)(nn * CDIM + c0 + ci) * 2 + t) * 4096 + (size_t)y * 64 + x0 + tx] = sm[ci][tx];
    }
}

// ---------------------------------------------------------------------------
extern "C" void kernel_launch(void* const* d_in, const int* in_sizes, int n_in,
                              void* d_out, int out_size) {
    (void)in_sizes; (void)n_in; (void)out_size;
    const float* q      = (const float*)d_in[0];
    const float* k      = (const float*)d_in[1];
    const float* v      = (const float*)d_in[2];
    const float* pos    = (const float*)d_in[3];
    const float* wl_in  = (const float*)d_in[4];
    const float* bl_in  = (const float*)d_in[5];
    const float* wl_out = (const float*)d_in[6];
    const float* bl_out = (const float*)d_in[7];
    const float* ws_in  = (const float*)d_in[8];
    const float* bs_in  = (const float*)d_in[9];
    const float* ws_out = (const float*)d_in[10];
    const float* bs_out = (const float*)d_in[11];
    float* out = (float*)d_out;

    float *px0, *px1, *px2, *pq, *pk, *pv, *po, *pm;
    cudaGetSymbolAddress((void**)&px0, g_x0);
    cudaGetSymbolAddress((void**)&px1, g_x1);
    cudaGetSymbolAddress((void**)&px2, g_x2);
    cudaGetSymbolAddress((void**)&pq,  g_qb);
    cudaGetSymbolAddress((void**)&pk,  g_kb);
    cudaGetSymbolAddress((void**)&pv,  g_vb);
    cudaGetSymbolAddress((void**)&po,  g_ob);
    cudaGetSymbolAddress((void**)&pm,  g_mb);

    dim3 gGather(16, 64, 4), bGather(32, 8);
    dim3 gGemm(4, 128);
    dim3 gAttn1(512, 8);
    dim3 gAttn2(4, 8, 32);

    // Phase 1: gather to long layout (+pos)
    gather_long<<<gGather, bGather>>>(q, k, v, pos);

    // Phase 2: MHA1 input projections (tensor cores, bf16 split)
    gemm_nt_tc<<<gGemm, 256>>>(px0, wl_in,              bl_in,       pq);
    gemm_nt_tc<<<gGemm, 256>>>(px1, wl_in + 256 * 256,  bl_in + 256, pk);
    gemm_nt_tc<<<gGemm, 256>>>(px2, wl_in + 512 * 256,  bl_in + 512, pv);

    // Phase 3: long attention
    attn1<<<gAttn1, 32>>>(pq, pk, pv, po);

    // Phase 4: MHA1 output projection
    gemm_nt_tc<<<gGemm, 256>>>(po, wl_out, bl_out, pm);

    // Phase 5: permute long -> short, add pos
    reindex_short<<<TOK, 256>>>();

    // Phase 6: MHA2 input projections (query and key share input g_x0)
    gemm_nt_tc<<<gGemm, 256>>>(px0, ws_in,              bs_in,       pq);
    gemm_nt_tc<<<gGemm, 256>>>(px0, ws_in + 256 * 256,  bs_in + 256, pk);
    gemm_nt_tc<<<gGemm, 256>>>(px2, ws_in + 512 * 256,  bs_in + 512, pv);

    // Phase 7: short attention (flash)
    attn2<<<gAttn2, 128>>>(pq, pk, pv, po);

    // Phase 8: MHA2 output projection + scatter to output layout
    gemm_nt_tc<<<gGemm, 256>>>(po, ws_out, bs_out, pm);
    scatter_out<<<gGather, bGather>>>(pm, out);
}

// round 4
// speedup vs baseline: 1.4624x; 1.1375x over previous
#include <cuda_runtime.h>
#include <cuda_bf16.h>
#include <cstdint>

// Problem constants
#define TOK   16384      // tokens per MHA stage (32*512 == 512*32)
#define CDIM  256
#define NHEAD 8
#define DHEAD 32
#define SCALE 0.17677669529663687f  // 1/sqrt(32)

// Scratch (static device globals — allocation-free per harness rules)
__device__ float g_x0[TOK * CDIM];
__device__ float g_x1[TOK * CDIM];
__device__ float g_x2[TOK * CDIM];
__device__ float g_p [TOK * CDIM];
__device__ float g_qb[TOK * CDIM];
__device__ float g_kb[TOK * CDIM];
__device__ float g_vb[TOK * CDIM];
__device__ float g_ob[TOK * CDIM];
__device__ float g_mb[TOK * CDIM];

// ---------------------------------------------------------------------------
// Gather: [n,c,t,h,w] -> long token layout [token= l*512+b, c]
// ---------------------------------------------------------------------------
__global__ void gather_long(const float* __restrict__ q, const float* __restrict__ k,
                            const float* __restrict__ v, const float* __restrict__ p) {
    int ct = blockIdx.x >> 1, xt = blockIdx.x & 1;
    int y  = blockIdx.y;
    int nn = blockIdx.z >> 1, t = blockIdx.z & 1;
    int c0 = ct * 32, x0 = xt * 32;
    __shared__ float sq[32][33], sk[32][33], sv[32][33], sp[32][33];
    int tx = threadIdx.x, ty = threadIdx.y;
    #pragma unroll
    for (int i = 0; i < 4; i++) {
        int ci = ty + i * 8;
        size_t idx = ((size_t)(nn * CDIM + c0 + ci) * 2 + t) * 4096 + (size_t)y * 64 + x0 + tx;
        float pv = p[idx];
        sq[ci][tx] = q[idx] + pv;
        sk[ci][tx] = k[idx] + pv;
        sv[ci][tx] = v[idx];
        sp[ci][tx] = pv;
    }
    __syncthreads();
    int bh = y >> 4, ih = y & 15;
    #pragma unroll
    for (int i = 0; i < 4; i++) {
        int xi = ty + i * 8;
        int x = x0 + xi;
        int bw = x >> 4, iw = x & 15;
        int token = (t * 16 + bh * 4 + bw) * 512 + nn * 256 + ih * 16 + iw;
        size_t o = (size_t)token * CDIM + c0 + tx;
        g_x0[o] = sq[tx][xi];
        g_x1[o] = sk[tx][xi];
        g_x2[o] = sv[tx][xi];
        g_p [o] = sp[tx][xi];
    }
}

// ---------------------------------------------------------------------------
// Tensor-core GEMM, truncation-split bf16 (hi/lo), double-buffered smem.
// Y[M,256] = X[M,256] @ W^T + bias ; BM=128 BN=64 BK=32 ; 256 thr, 8 warps.
// hi = trunc16(x) (PRMT-packed), lo = x - hi (cvt.rn.bf16x2-packed).
// hi*hi + hi*lo + lo*hi with fp32 accum -> ~1e-5 relative error.
// grid (4, 128)  block (256)
// ---------------------------------------------------------------------------
#define LDSR 40   // padded smem row stride in bf16 (80B: ldmatrix conflict-free)

__device__ __forceinline__ void mma_bf16(float* d, const uint32_t* a, const uint32_t* b) {
    asm volatile(
        "mma.sync.aligned.m16n8k16.row.col.f32.bf16.bf16.f32 "
        "{%0,%1,%2,%3}, {%4,%5,%6,%7}, {%8,%9}, {%0,%1,%2,%3};"
        : "+f"(d[0]), "+f"(d[1]), "+f"(d[2]), "+f"(d[3])
        : "r"(a[0]), "r"(a[1]), "r"(a[2]), "r"(a[3]), "r"(b[0]), "r"(b[1]));
}

__device__ __forceinline__ void ldsm_x4(uint32_t* r, const __nv_bfloat16* p) {
    uint32_t addr = (uint32_t)__cvta_generic_to_shared(p);
    asm volatile("ldmatrix.sync.aligned.m8n8.x4.shared.b16 {%0,%1,%2,%3}, [%4];"
                 : "=r"(r[0]), "=r"(r[1]), "=r"(r[2]), "=r"(r[3]) : "r"(addr));
}

__device__ __forceinline__ void ldsm_x2(uint32_t* r, const __nv_bfloat16* p) {
    uint32_t addr = (uint32_t)__cvta_generic_to_shared(p);
    asm volatile("ldmatrix.sync.aligned.m8n8.x2.shared.b16 {%0,%1}, [%2];"
                 : "=r"(r[0]), "=r"(r[1]) : "r"(addr));
}

// Convert float4 (4 consecutive k) -> 2 packed hi words + 2 packed lo words,
// store with STS.64 each. hi = truncated top-16 bits (exact residual in lo).
__device__ __forceinline__ void split_store4(__nv_bfloat16* hp, __nv_bfloat16* lp, float4 v) {
    uint32_t ux = __float_as_uint(v.x), uy = __float_as_uint(v.y);
    uint32_t uz = __float_as_uint(v.z), uw = __float_as_uint(v.w);
    uint32_t hi01 = __byte_perm(ux, uy, 0x7632);
    uint32_t hi23 = __byte_perm(uz, uw, 0x7632);
    float l0 = v.x - __uint_as_float(ux & 0xFFFF0000u);
    float l1 = v.y - __uint_as_float(uy & 0xFFFF0000u);
    float l2 = v.z - __uint_as_float(uz & 0xFFFF0000u);
    float l3 = v.w - __uint_as_float(uw & 0xFFFF0000u);
    __nv_bfloat162 lo01 = __floats2bfloat162_rn(l0, l1);
    __nv_bfloat162 lo23 = __floats2bfloat162_rn(l2, l3);
    uint2 hw; hw.x = hi01; hw.y = hi23;
    uint2 lw; lw.x = *(uint32_t*)&lo01; lw.y = *(uint32_t*)&lo23;
    *(uint2*)hp = hw;
    *(uint2*)lp = lw;
}

__global__ __launch_bounds__(256) void gemm_nt_tc(const float* __restrict__ X,
                                                  const float* __restrict__ Wm,
                                                  const float* __restrict__ bias,
                                                  float* __restrict__ Y) {
    __shared__ __nv_bfloat16 As_hi[2][128 * LDSR], As_lo[2][128 * LDSR];
    __shared__ __nv_bfloat16 Bs_hi[2][64 * LDSR],  Bs_lo[2][64 * LDSR];

    int tid  = threadIdx.x;
    int warp = tid >> 5, lane = tid & 31;
    int m0 = blockIdx.y * 128, n0 = blockIdx.x * 64;
    int wm = (warp >> 1) * 32;     // 4 warps over m
    int wn = (warp & 1) * 32;      // 2 warps over n

    float acc[2][4][4];
    #pragma unroll
    for (int mi = 0; mi < 2; mi++)
        #pragma unroll
        for (int ni = 0; ni < 4; ni++)
            #pragma unroll
            for (int e = 0; e < 4; e++) acc[mi][ni][e] = 0.f;

    const float4* X4 = (const float4*)X;
    const float4* W4 = (const float4*)Wm;
    int lrow  = tid >> 3;   // 0..31
    int lcol4 = tid & 7;    // float4 col within 32-wide K tile

    // ldmatrix source offsets (per buffer applied later)
    int al16 = lane & 15;
    int offA = (wm + al16) * LDSR + (lane >> 4) * 8;
    int offB = (wn + (al16 & 7)) * LDSR + (al16 >> 3) * 8;

    // Prefetch kt = 0
    float4 xa[4], wb[2];
    #pragma unroll
    for (int i = 0; i < 4; i++)
        xa[i] = X4[(size_t)(m0 + lrow + i * 32) * 64 + lcol4];
    #pragma unroll
    for (int i = 0; i < 2; i++)
        wb[i] = W4[(size_t)(n0 + lrow + i * 32) * 64 + lcol4];

    for (int kt = 0; kt < 8; kt++) {
        int buf = kt & 1;
        // Stage current tile (converted, packed, STS.64)
        #pragma unroll
        for (int i = 0; i < 4; i++) {
            int r = lrow + i * 32;
            split_store4(&As_hi[buf][r * LDSR + lcol4 * 4],
                         &As_lo[buf][r * LDSR + lcol4 * 4], xa[i]);
        }
        #pragma unroll
        for (int i = 0; i < 2; i++) {
            int r = lrow + i * 32;
            split_store4(&Bs_hi[buf][r * LDSR + lcol4 * 4],
                         &Bs_lo[buf][r * LDSR + lcol4 * 4], wb[i]);
        }
        __syncthreads();

        // Prefetch next tile from gmem (overlaps MMA below)
        if (kt < 7) {
            #pragma unroll
            for (int i = 0; i < 4; i++)
                xa[i] = X4[(size_t)(m0 + lrow + i * 32) * 64 + (kt + 1) * 8 + lcol4];
            #pragma unroll
            for (int i = 0; i < 2; i++)
                wb[i] = W4[(size_t)(n0 + lrow + i * 32) * 64 + (kt + 1) * 8 + lcol4];
        }

        const __nv_bfloat16* pa_hi0 = &As_hi[buf][offA];
        const __nv_bfloat16* pa_lo0 = &As_lo[buf][offA];
        const __nv_bfloat16* pb_hi0 = &Bs_hi[buf][offB];
        const __nv_bfloat16* pb_lo0 = &Bs_lo[buf][offB];

        #pragma unroll
        for (int kk = 0; kk < 2; kk++) {
            int ko = kk * 16;
            uint32_t ah[2][4], al[2][4];
            #pragma unroll
            for (int mi = 0; mi < 2; mi++) {
                ldsm_x4(ah[mi], pa_hi0 + mi * 16 * LDSR + ko);
                ldsm_x4(al[mi], pa_lo0 + mi * 16 * LDSR + ko);
            }
            uint32_t bh[4][2], bl[4][2];
            #pragma unroll
            for (int ni = 0; ni < 4; ni++) {
                ldsm_x2(bh[ni], pb_hi0 + ni * 8 * LDSR + ko);
                ldsm_x2(bl[ni], pb_lo0 + ni * 8 * LDSR + ko);
            }
            #pragma unroll
            for (int mi = 0; mi < 2; mi++)
                #pragma unroll
                for (int ni = 0; ni < 4; ni++) {
                    mma_bf16(acc[mi][ni], ah[mi], bh[ni]);
                    mma_bf16(acc[mi][ni], ah[mi], bl[ni]);
                    mma_bf16(acc[mi][ni], al[mi], bh[ni]);
                }
        }
        // Single sync per iteration: compute(buf) at kt precedes the sync at
        // kt+1, which precedes any re-store of buf at kt+2 -> no extra sync.
    }

    // Epilogue: C fragment m16n8 layout -> Y, with bias
    int cr = lane >> 2;           // 0..7
    int cc = (lane & 3) * 2;      // 0,2,4,6
    #pragma unroll
    for (int mi = 0; mi < 2; mi++) {
        #pragma unroll
        for (int ni = 0; ni < 4; ni++) {
            int col = n0 + wn + ni * 8 + cc;
            float b0 = bias[col], b1 = bias[col + 1];
            int row0 = m0 + wm + mi * 16 + cr;
            float2 o0 = make_float2(acc[mi][ni][0] + b0, acc[mi][ni][1] + b1);
            float2 o1 = make_float2(acc[mi][ni][2] + b0, acc[mi][ni][3] + b1);
            *(float2*)&Y[(size_t)row0 * CDIM + col]       = o0;
            *(float2*)&Y[(size_t)(row0 + 8) * CDIM + col] = o1;
        }
    }
}

// ---------------------------------------------------------------------------
// Attention #1 (long): Lq=Lk=32, d=32; one warp per (b,h); thread = query row.
// grid (512, 8) block (32)
// ---------------------------------------------------------------------------
__global__ void attn1(const float* __restrict__ Q, const float* __restrict__ K,
                      const float* __restrict__ V, float* __restrict__ O) {
    int b = blockIdx.x, h = blockIdx.y;
    size_t base = (size_t)b * CDIM + h * DHEAD;
    __shared__ float Ks[32][36], Vs[32][36];
    int tid = threadIdx.x;
    for (int r = 0; r < 32; r++) {
        size_t idx = (size_t)r * 131072 + base + tid;
        Ks[r][tid] = K[idx];
        Vs[r][tid] = V[idx];
    }
    __syncthreads();
    float q[32];
    const float4* q4 = (const float4*)(Q + (size_t)tid * 131072 + base);
    #pragma unroll
    for (int d4 = 0; d4 < 8; d4++) {
        float4 qq = q4[d4];
        q[d4 * 4 + 0] = qq.x * SCALE; q[d4 * 4 + 1] = qq.y * SCALE;
        q[d4 * 4 + 2] = qq.z * SCALE; q[d4 * 4 + 3] = qq.w * SCALE;
    }
    float s[32];
    float m = -1e30f;
    #pragma unroll
    for (int j = 0; j < 32; j++) {
        const float4* kr = (const float4*)Ks[j];
        float a = 0.f;
        #pragma unroll
        for (int d4 = 0; d4 < 8; d4++) {
            float4 kv = kr[d4];
            a += q[d4 * 4 + 0] * kv.x + q[d4 * 4 + 1] * kv.y
               + q[d4 * 4 + 2] * kv.z + q[d4 * 4 + 3] * kv.w;
        }
        s[j] = a;
        m = fmaxf(m, a);
    }
    float lsum = 0.f;
    #pragma unroll
    for (int j = 0; j < 32; j++) { s[j] = __expf(s[j] - m); lsum += s[j]; }
    float acc[32];
    #pragma unroll
    for (int d = 0; d < 32; d++) acc[d] = 0.f;
    #pragma unroll
    for (int j = 0; j < 32; j++) {
        const float4* vr = (const float4*)Vs[j];
        float pj = s[j];
        #pragma unroll
        for (int d4 = 0; d4 < 8; d4++) {
            float4 vv = vr[d4];
            acc[d4 * 4 + 0] += pj * vv.x; acc[d4 * 4 + 1] += pj * vv.y;
            acc[d4 * 4 + 2] += pj * vv.z; acc[d4 * 4 + 3] += pj * vv.w;
        }
    }
    float inv = 1.f / lsum;
    float4* o4 = (float4*)(O + (size_t)tid * 131072 + base);
    #pragma unroll
    for (int d4 = 0; d4 < 8; d4++) {
        float4 oo;
        oo.x = acc[d4 * 4 + 0] * inv; oo.y = acc[d4 * 4 + 1] * inv;
        oo.z = acc[d4 * 4 + 2] * inv; oo.w = acc[d4 * 4 + 3] * inv;
        o4[d4] = oo;
    }
}

// ---------------------------------------------------------------------------
// Re-index long -> short, add pos
// grid (16384) block (256)
// ---------------------------------------------------------------------------
__global__ void reindex_short() {
    int token2 = blockIdx.x;
    int s = token2 >> 5, b2 = token2 & 31;
    int t = s >> 8, rem = s & 255, ih = rem >> 4, iw = rem & 15;
    int nn = b2 >> 4, rr = b2 & 15, bh = rr >> 2, bw = rr & 3;
    int token = (t * 16 + bh * 4 + bw) * 512 + nn * 256 + ih * 16 + iw;
    int c = threadIdx.x;
    size_t si = (size_t)token * CDIM + c;
    size_t di = (size_t)token2 * CDIM + c;
    float x = g_mb[si];
    float pp = g_p[si];
    g_x0[di] = x + pp;
    g_x2[di] = x;
}

// ---------------------------------------------------------------------------
// Attention #2 (short): L=512, d=32; flash-style, thread = query row.
// grid (4, 8, 32) block (128)
// ---------------------------------------------------------------------------
__global__ __launch_bounds__(128) void attn2(const float* __restrict__ Q,
                                             const float* __restrict__ K,
                                             const float* __restrict__ V,
                                             float* __restrict__ O) {
    int qt = blockIdx.x, h = blockIdx.y, b2 = blockIdx.z;
    size_t base = (size_t)b2 * CDIM + h * DHEAD;
    int tid = threadIdx.x;
    int l = qt * 128 + tid;
    __shared__ float Ks[64][36], Vs[64][36];

    float q[32], acc[32];
    const float4* q4 = (const float4*)(Q + (size_t)l * 8192 + base);
    #pragma unroll
    for (int d4 = 0; d4 < 8; d4++) {
        float4 qq = q4[d4];
        q[d4 * 4 + 0] = qq.x * SCALE; q[d4 * 4 + 1] = qq.y * SCALE;
        q[d4 * 4 + 2] = qq.z * SCALE; q[d4 * 4 + 3] = qq.w * SCALE;
    }
    #pragma unroll
    for (int d = 0; d < 32; d++) acc[d] = 0.f;
    float m = -1e30f, lsum = 0.f;

    for (int kt = 0; kt < 8; kt++) {
        int k0 = kt * 64;
        __syncthreads();
        #pragma unroll
        for (int i = 0; i < 16; i++) {
            int r = (tid >> 5) + i * 4;
            int col = tid & 31;
            size_t idx = (size_t)(k0 + r) * 8192 + base + col;
            Ks[r][col] = K[idx];
            Vs[r][col] = V[idx];
        }
        __syncthreads();
        float s[64];
        float mt = -1e30f;
        #pragma unroll
        for (int j = 0; j < 64; j++) {
            const float4* kr = (const float4*)Ks[j];
            float a = 0.f;
            #pragma unroll
            for (int d4 = 0; d4 < 8; d4++) {
                float4 kv = kr[d4];
                a += q[d4 * 4 + 0] * kv.x + q[d4 * 4 + 1] * kv.y
                   + q[d4 * 4 + 2] * kv.z + q[d4 * 4 + 3] * kv.w;
            }
            s[j] = a;
            mt = fmaxf(mt, a);
        }
        float mnew = fmaxf(m, mt);
        float corr = __expf(m - mnew);
        lsum *= corr;
        #pragma unroll
        for (int d = 0; d < 32; d++) acc[d] *= corr;
        #pragma unroll
        for (int j = 0; j < 64; j++) {
            float pj = __expf(s[j] - mnew);
            lsum += pj;
            s[j] = pj;
        }
        #pragma unroll
        for (int j = 0; j < 64; j++) {
            const float4* vr = (const float4*)Vs[j];
            float pj = s[j];
            #pragma unroll
            for (int d4 = 0; d4 < 8; d4++) {
                float4 vv = vr[d4];
                acc[d4 * 4 + 0] += pj * vv.x; acc[d4 * 4 + 1] += pj * vv.y;
                acc[d4 * 4 + 2] += pj * vv.z; acc[d4 * 4 + 3] += pj * vv.w;
            }
        }
        m = mnew;
    }
    float inv = 1.f / lsum;
    float4* o4 = (float4*)(O + (size_t)l * 8192 + base);
    #pragma unroll
    for (int d4 = 0; d4 < 8; d4++) {
        float4 oo;
        oo.x = acc[d4 * 4 + 0] * inv; oo.y = acc[d4 * 4 + 1] * inv;
        oo.z = acc[d4 * 4 + 2] * inv; oo.w = acc[d4 * 4 + 3] * inv;
        o4[d4] = oo;
    }
}

// ---------------------------------------------------------------------------
// Scatter: short token layout -> output [n,c,t,h,w]
// grid (16, 64, 4) block (32, 8)
// ---------------------------------------------------------------------------
__global__ void scatter_out(const float* __restrict__ src, float* __restrict__ out) {
    int ct = blockIdx.x >> 1, xt = blockIdx.x & 1;
    int y  = blockIdx.y;
    int nn = blockIdx.z >> 1, t = blockIdx.z & 1;
    int c0 = ct * 32, x0 = xt * 32;
    int bh = y >> 4, ih = y & 15;
    __shared__ float sm[32][33];
    int tx = threadIdx.x, ty = threadIdx.y;
    #pragma unroll
    for (int i = 0; i < 4; i++) {
        int xi = ty + i * 8;
        int x = x0 + xi;
        int bw = x >> 4, iw = x & 15;
        int s  = t * 256 + ih * 16 + iw;
        int b2 = nn * 16 + bh * 4 + bw;
        int token2 = s * 32 + b2;
        sm[tx][xi] = src[(size_t)token2 * CDIM + c0 + tx];
    }
    __syncthreads();
    #pragma unroll
    for (int i = 0; i < 4; i++) {
        int ci = ty + i * 8;
        out[((size_t)(nn * CDIM + c0 + ci) * 2 + t) * 4096 + (size_t)y * 64 + x0 + tx] = sm[ci][tx];
    }
}

// ---------------------------------------------------------------------------
extern "C" void kernel_launch(void* const* d_in, const int* in_sizes, int n_in,
                              void* d_out, int out_size) {
    (void)in_sizes; (void)n_in; (void)out_size;
    const float* q      = (const float*)d_in[0];
    const float* k      = (const float*)d_in[1];
    const float* v      = (const float*)d_in[2];
    const float* pos    = (const float*)d_in[3];
    const float* wl_in  = (const float*)d_in[4];
    const float* bl_in  = (const float*)d_in[5];
    const float* wl_out = (const float*)d_in[6];
    const float* bl_out = (const float*)d_in[7];
    const float* ws_in  = (const float*)d_in[8];
    const float* bs_in  = (const float*)d_in[9];
    const float* ws_out = (const float*)d_in[10];
    const float* bs_out = (const float*)d_in[11];
    float* out = (float*)d_out;

    float *px0, *px1, *px2, *pq, *pk, *pv, *po, *pm;
    cudaGetSymbolAddress((void**)&px0, g_x0);
    cudaGetSymbolAddress((void**)&px1, g_x1);
    cudaGetSymbolAddress((void**)&px2, g_x2);
    cudaGetSymbolAddress((void**)&pq,  g_qb);
    cudaGetSymbolAddress((void**)&pk,  g_kb);
    cudaGetSymbolAddress((void**)&pv,  g_vb);
    cudaGetSymbolAddress((void**)&po,  g_ob);
    cudaGetSymbolAddress((void**)&pm,  g_mb);

    dim3 gGather(16, 64, 4), bGather(32, 8);
    dim3 gGemm(4, 128);
    dim3 gAttn1(512, 8);
    dim3 gAttn2(4, 8, 32);

    // Phase 1: gather to long layout (+pos)
    gather_long<<<gGather, bGather>>>(q, k, v, pos);

    // Phase 2: MHA1 input projections (tensor cores, truncation split)
    gemm_nt_tc<<<gGemm, 256>>>(px0, wl_in,              bl_in,       pq);
    gemm_nt_tc<<<gGemm, 256>>>(px1, wl_in + 256 * 256,  bl_in + 256, pk);
    gemm_nt_tc<<<gGemm, 256>>>(px2, wl_in + 512 * 256,  bl_in + 512, pv);

    // Phase 3: long attention
    attn1<<<gAttn1, 32>>>(pq, pk, pv, po);

    // Phase 4: MHA1 output projection
    gemm_nt_tc<<<gGemm, 256>>>(po, wl_out, bl_out, pm);

    // Phase 5: permute long -> short, add pos
    reindex_short<<<TOK, 256>>>();

    // Phase 6: MHA2 input projections (query and key share input g_x0)
    gemm_nt_tc<<<gGemm, 256>>>(px0, ws_in,              bs_in,       pq);
    gemm_nt_tc<<<gGemm, 256>>>(px0, ws_in + 256 * 256,  bs_in + 256, pk);
    gemm_nt_tc<<<gGemm, 256>>>(px2, ws_in + 512 * 256,  bs_in + 512, pv);

    // Phase 7: short attention (flash)
    attn2<<<gAttn2, 128>>>(pq, pk, pv, po);

    // Phase 8: MHA2 output projection + scatter to output layout
    gemm_nt_tc<<<gGemm, 256>>>(po, ws_out, bs_out, pm);
    scatter_out<<<gGather, bGather>>>(pm, out);
}

// round 5
// speedup vs baseline: 2.4978x; 1.7080x over previous
#include <cuda_runtime.h>
#include <cuda_bf16.h>
#include <cstdint>

// Problem constants
#define TOK   16384      // tokens per MHA stage (32*512 == 512*32)
#define CDIM  256
#define NHEAD 8
#define DHEAD 32
#define SCALE 0.17677669529663687f  // 1/sqrt(32)

// Scratch (static device globals — allocation-free per harness rules)
__device__ float g_x0[TOK * CDIM];
__device__ float g_x1[TOK * CDIM];
__device__ float g_x2[TOK * CDIM];
__device__ float g_p [TOK * CDIM];
__device__ float g_qb[TOK * CDIM];
__device__ float g_kb[TOK * CDIM];
__device__ float g_vb[TOK * CDIM];
__device__ float g_ob[TOK * CDIM];
__device__ float g_mb[TOK * CDIM];

// ---------------------------------------------------------------------------
// Common MMA helpers
// ---------------------------------------------------------------------------
#define LDSR 40   // padded smem row stride in bf16 (80B: ldmatrix conflict-free)

__device__ __forceinline__ void mma_bf16(float* d, const uint32_t* a, const uint32_t* b) {
    asm volatile(
        "mma.sync.aligned.m16n8k16.row.col.f32.bf16.bf16.f32 "
        "{%0,%1,%2,%3}, {%4,%5,%6,%7}, {%8,%9}, {%0,%1,%2,%3};"
        : "+f"(d[0]), "+f"(d[1]), "+f"(d[2]), "+f"(d[3])
        : "r"(a[0]), "r"(a[1]), "r"(a[2]), "r"(a[3]), "r"(b[0]), "r"(b[1]));
}

__device__ __forceinline__ void ldsm_x4(uint32_t* r, const __nv_bfloat16* p) {
    uint32_t addr = (uint32_t)__cvta_generic_to_shared(p);
    asm volatile("ldmatrix.sync.aligned.m8n8.x4.shared.b16 {%0,%1,%2,%3}, [%4];"
                 : "=r"(r[0]), "=r"(r[1]), "=r"(r[2]), "=r"(r[3]) : "r"(addr));
}

__device__ __forceinline__ void ldsm_x2(uint32_t* r, const __nv_bfloat16* p) {
    uint32_t addr = (uint32_t)__cvta_generic_to_shared(p);
    asm volatile("ldmatrix.sync.aligned.m8n8.x2.shared.b16 {%0,%1}, [%2];"
                 : "=r"(r[0]), "=r"(r[1]) : "r"(addr));
}

__device__ __forceinline__ void ldsm_x2_trans(uint32_t* r, const __nv_bfloat16* p) {
    uint32_t addr = (uint32_t)__cvta_generic_to_shared(p);
    asm volatile("ldmatrix.sync.aligned.m8n8.x2.trans.shared.b16 {%0,%1}, [%2];"
                 : "=r"(r[0]), "=r"(r[1]) : "r"(addr));
}

// Truncation split: hi = top-16 bits of fp32 (packed via PRMT), lo = rn(x - hi).
__device__ __forceinline__ void pack_split(float x, float y, uint32_t* hi, uint32_t* lo) {
    uint32_t ux = __float_as_uint(x), uy = __float_as_uint(y);
    *hi = __byte_perm(ux, uy, 0x7632);
    float lx = x - __uint_as_float(ux & 0xFFFF0000u);
    float ly = y - __uint_as_float(uy & 0xFFFF0000u);
    __nv_bfloat162 lp = __floats2bfloat162_rn(lx, ly);
    *lo = *(uint32_t*)&lp;
}

// float4 (4 consecutive k) -> 2 packed hi words + 2 packed lo words, STS.64.
__device__ __forceinline__ void split_store4(__nv_bfloat16* hp, __nv_bfloat16* lp, float4 v) {
    uint32_t ux = __float_as_uint(v.x), uy = __float_as_uint(v.y);
    uint32_t uz = __float_as_uint(v.z), uw = __float_as_uint(v.w);
    uint32_t hi01 = __byte_perm(ux, uy, 0x7632);
    uint32_t hi23 = __byte_perm(uz, uw, 0x7632);
    float l0 = v.x - __uint_as_float(ux & 0xFFFF0000u);
    float l1 = v.y - __uint_as_float(uy & 0xFFFF0000u);
    float l2 = v.z - __uint_as_float(uz & 0xFFFF0000u);
    float l3 = v.w - __uint_as_float(uw & 0xFFFF0000u);
    __nv_bfloat162 lo01 = __floats2bfloat162_rn(l0, l1);
    __nv_bfloat162 lo23 = __floats2bfloat162_rn(l2, l3);
    uint2 hw; hw.x = hi01; hw.y = hi23;
    uint2 lw; lw.x = *(uint32_t*)&lo01; lw.y = *(uint32_t*)&lo23;
    *(uint2*)hp = hw;
    *(uint2*)lp = lw;
}

// ---------------------------------------------------------------------------
// Gather: [n,c,t,h,w] -> long token layout [token= l*512+b, c]
// ---------------------------------------------------------------------------
__global__ void gather_long(const float* __restrict__ q, const float* __restrict__ k,
                            const float* __restrict__ v, const float* __restrict__ p) {
    int ct = blockIdx.x >> 1, xt = blockIdx.x & 1;
    int y  = blockIdx.y;
    int nn = blockIdx.z >> 1, t = blockIdx.z & 1;
    int c0 = ct * 32, x0 = xt * 32;
    __shared__ float sq[32][33], sk[32][33], sv[32][33], sp[32][33];
    int tx = threadIdx.x, ty = threadIdx.y;
    #pragma unroll
    for (int i = 0; i < 4; i++) {
        int ci = ty + i * 8;
        size_t idx = ((size_t)(nn * CDIM + c0 + ci) * 2 + t) * 4096 + (size_t)y * 64 + x0 + tx;
        float pv = p[idx];
        sq[ci][tx] = q[idx] + pv;
        sk[ci][tx] = k[idx] + pv;
        sv[ci][tx] = v[idx];
        sp[ci][tx] = pv;
    }
    __syncthreads();
    int bh = y >> 4, ih = y & 15;
    #pragma unroll
    for (int i = 0; i < 4; i++) {
        int xi = ty + i * 8;
        int x = x0 + xi;
        int bw = x >> 4, iw = x & 15;
        int token = (t * 16 + bh * 4 + bw) * 512 + nn * 256 + ih * 16 + iw;
        size_t o = (size_t)token * CDIM + c0 + tx;
        g_x0[o] = sq[tx][xi];
        g_x1[o] = sk[tx][xi];
        g_x2[o] = sv[tx][xi];
        g_p [o] = sp[tx][xi];
    }
}

// ---------------------------------------------------------------------------
// Tensor-core GEMM, truncation-split bf16, double-buffered smem.
// grid (4, 128)  block (256)
// ---------------------------------------------------------------------------
__global__ __launch_bounds__(256) void gemm_nt_tc(const float* __restrict__ X,
                                                  const float* __restrict__ Wm,
                                                  const float* __restrict__ bias,
                                                  float* __restrict__ Y) {
    __shared__ __nv_bfloat16 As_hi[2][128 * LDSR], As_lo[2][128 * LDSR];
    __shared__ __nv_bfloat16 Bs_hi[2][64 * LDSR],  Bs_lo[2][64 * LDSR];

    int tid  = threadIdx.x;
    int warp = tid >> 5, lane = tid & 31;
    int m0 = blockIdx.y * 128, n0 = blockIdx.x * 64;
    int wm = (warp >> 1) * 32;
    int wn = (warp & 1) * 32;

    float acc[2][4][4];
    #pragma unroll
    for (int mi = 0; mi < 2; mi++)
        #pragma unroll
        for (int ni = 0; ni < 4; ni++)
            #pragma unroll
            for (int e = 0; e < 4; e++) acc[mi][ni][e] = 0.f;

    const float4* X4 = (const float4*)X;
    const float4* W4 = (const float4*)Wm;
    int lrow  = tid >> 3;
    int lcol4 = tid & 7;

    int al16 = lane & 15;
    int offA = (wm + al16) * LDSR + (lane >> 4) * 8;
    int offB = (wn + (al16 & 7)) * LDSR + (al16 >> 3) * 8;

    float4 xa[4], wb[2];
    #pragma unroll
    for (int i = 0; i < 4; i++)
        xa[i] = X4[(size_t)(m0 + lrow + i * 32) * 64 + lcol4];
    #pragma unroll
    for (int i = 0; i < 2; i++)
        wb[i] = W4[(size_t)(n0 + lrow + i * 32) * 64 + lcol4];

    for (int kt = 0; kt < 8; kt++) {
        int buf = kt & 1;
        #pragma unroll
        for (int i = 0; i < 4; i++) {
            int r = lrow + i * 32;
            split_store4(&As_hi[buf][r * LDSR + lcol4 * 4],
                         &As_lo[buf][r * LDSR + lcol4 * 4], xa[i]);
        }
        #pragma unroll
        for (int i = 0; i < 2; i++) {
            int r = lrow + i * 32;
            split_store4(&Bs_hi[buf][r * LDSR + lcol4 * 4],
                         &Bs_lo[buf][r * LDSR + lcol4 * 4], wb[i]);
        }
        __syncthreads();

        if (kt < 7) {
            #pragma unroll
            for (int i = 0; i < 4; i++)
                xa[i] = X4[(size_t)(m0 + lrow + i * 32) * 64 + (kt + 1) * 8 + lcol4];
            #pragma unroll
            for (int i = 0; i < 2; i++)
                wb[i] = W4[(size_t)(n0 + lrow + i * 32) * 64 + (kt + 1) * 8 + lcol4];
        }

        const __nv_bfloat16* pa_hi0 = &As_hi[buf][offA];
        const __nv_bfloat16* pa_lo0 = &As_lo[buf][offA];
        const __nv_bfloat16* pb_hi0 = &Bs_hi[buf][offB];
        const __nv_bfloat16* pb_lo0 = &Bs_lo[buf][offB];

        #pragma unroll
        for (int kk = 0; kk < 2; kk++) {
            int ko = kk * 16;
            uint32_t ah[2][4], al[2][4];
            #pragma unroll
            for (int mi = 0; mi < 2; mi++) {
                ldsm_x4(ah[mi], pa_hi0 + mi * 16 * LDSR + ko);
                ldsm_x4(al[mi], pa_lo0 + mi * 16 * LDSR + ko);
            }
            uint32_t bh[4][2], bl[4][2];
            #pragma unroll
            for (int ni = 0; ni < 4; ni++) {
                ldsm_x2(bh[ni], pb_hi0 + ni * 8 * LDSR + ko);
                ldsm_x2(bl[ni], pb_lo0 + ni * 8 * LDSR + ko);
            }
            #pragma unroll
            for (int mi = 0; mi < 2; mi++)
                #pragma unroll
                for (int ni = 0; ni < 4; ni++) {
                    mma_bf16(acc[mi][ni], ah[mi], bh[ni]);
                    mma_bf16(acc[mi][ni], ah[mi], bl[ni]);
                    mma_bf16(acc[mi][ni], al[mi], bh[ni]);
                }
        }
    }

    int cr = lane >> 2;
    int cc = (lane & 3) * 2;
    #pragma unroll
    for (int mi = 0; mi < 2; mi++) {
        #pragma unroll
        for (int ni = 0; ni < 4; ni++) {
            int col = n0 + wn + ni * 8 + cc;
            float b0 = bias[col], b1 = bias[col + 1];
            int row0 = m0 + wm + mi * 16 + cr;
            float2 o0 = make_float2(acc[mi][ni][0] + b0, acc[mi][ni][1] + b1);
            float2 o1 = make_float2(acc[mi][ni][2] + b0, acc[mi][ni][3] + b1);
            *(float2*)&Y[(size_t)row0 * CDIM + col]       = o0;
            *(float2*)&Y[(size_t)(row0 + 8) * CDIM + col] = o1;
        }
    }
}

// ---------------------------------------------------------------------------
// Attention #1 (long): Lq=Lk=32, d=32; one warp per (b,h); thread = query row.
// grid (512, 8) block (32)
// ---------------------------------------------------------------------------
__global__ void attn1(const float* __restrict__ Q, const float* __restrict__ K,
                      const float* __restrict__ V, float* __restrict__ O) {
    int b = blockIdx.x, h = blockIdx.y;
    size_t base = (size_t)b * CDIM + h * DHEAD;
    __shared__ float Ks[32][36], Vs[32][36];
    int tid = threadIdx.x;
    for (int r = 0; r < 32; r++) {
        size_t idx = (size_t)r * 131072 + base + tid;
        Ks[r][tid] = K[idx];
        Vs[r][tid] = V[idx];
    }
    __syncthreads();
    float q[32];
    const float4* q4 = (const float4*)(Q + (size_t)tid * 131072 + base);
    #pragma unroll
    for (int d4 = 0; d4 < 8; d4++) {
        float4 qq = q4[d4];
        q[d4 * 4 + 0] = qq.x * SCALE; q[d4 * 4 + 1] = qq.y * SCALE;
        q[d4 * 4 + 2] = qq.z * SCALE; q[d4 * 4 + 3] = qq.w * SCALE;
    }
    float s[32];
    float m = -1e30f;
    #pragma unroll
    for (int j = 0; j < 32; j++) {
        const float4* kr = (const float4*)Ks[j];
        float a = 0.f;
        #pragma unroll
        for (int d4 = 0; d4 < 8; d4++) {
            float4 kv = kr[d4];
            a += q[d4 * 4 + 0] * kv.x + q[d4 * 4 + 1] * kv.y
               + q[d4 * 4 + 2] * kv.z + q[d4 * 4 + 3] * kv.w;
        }
        s[j] = a;
        m = fmaxf(m, a);
    }
    float lsum = 0.f;
    #pragma unroll
    for (int j = 0; j < 32; j++) { s[j] = __expf(s[j] - m); lsum += s[j]; }
    float acc[32];
    #pragma unroll
    for (int d = 0; d < 32; d++) acc[d] = 0.f;
    #pragma unroll
    for (int j = 0; j < 32; j++) {
        const float4* vr = (const float4*)Vs[j];
        float pj = s[j];
        #pragma unroll
        for (int d4 = 0; d4 < 8; d4++) {
            float4 vv = vr[d4];
            acc[d4 * 4 + 0] += pj * vv.x; acc[d4 * 4 + 1] += pj * vv.y;
            acc[d4 * 4 + 2] += pj * vv.z; acc[d4 * 4 + 3] += pj * vv.w;
        }
    }
    float inv = 1.f / lsum;
    float4* o4 = (float4*)(O + (size_t)tid * 131072 + base);
    #pragma unroll
    for (int d4 = 0; d4 < 8; d4++) {
        float4 oo;
        oo.x = acc[d4 * 4 + 0] * inv; oo.y = acc[d4 * 4 + 1] * inv;
        oo.z = acc[d4 * 4 + 2] * inv; oo.w = acc[d4 * 4 + 3] * inv;
        o4[d4] = oo;
    }
}

// ---------------------------------------------------------------------------
// Re-index long -> short, add pos
// grid (16384) block (256)
// ---------------------------------------------------------------------------
__global__ void reindex_short() {
    int token2 = blockIdx.x;
    int s = token2 >> 5, b2 = token2 & 31;
    int t = s >> 8, rem = s & 255, ih = rem >> 4, iw = rem & 15;
    int nn = b2 >> 4, rr = b2 & 15, bh = rr >> 2, bw = rr & 3;
    int token = (t * 16 + bh * 4 + bw) * 512 + nn * 256 + ih * 16 + iw;
    int c = threadIdx.x;
    size_t si = (size_t)token * CDIM + c;
    size_t di = (size_t)token2 * CDIM + c;
    float x = g_mb[si];
    float pp = g_p[si];
    g_x0[di] = x + pp;
    g_x2[di] = x;
}

// ---------------------------------------------------------------------------
// Attention #2 (short): FlashAttention-2 on mma.sync, truncation-split bf16.
// L=512, d=32. Block = 256 thr (8 warps) handles 128 queries of one (b2,h);
// warp owns 16 query rows. K/V tiles of 64 keys staged to smem as bf16 hi/lo.
// S = 3-term split MMA; online softmax in C-fragment registers; P repacked
// into A fragments with no shuffles; PV = 3-term split MMA with V via
// ldmatrix.trans. grid (4, 8, 32) block (256)
// ---------------------------------------------------------------------------
__global__ __launch_bounds__(256) void attn2_tc(const float* __restrict__ Q,
                                                const float* __restrict__ K,
                                                const float* __restrict__ V,
                                                float* __restrict__ O) {
    int qt = blockIdx.x, h = blockIdx.y, b2 = blockIdx.z;
    size_t base = (size_t)b2 * CDIM + h * DHEAD;
    __shared__ __nv_bfloat16 Kh[64 * LDSR], Kl[64 * LDSR];
    __shared__ __nv_bfloat16 Vh[64 * LDSR], Vl[64 * LDSR];

    int tid = threadIdx.x, warp = tid >> 5, lane = tid & 31;
    int al16 = lane & 15;
    int r  = lane >> 2;          // fragment row 0..7
    int cq = (lane & 3) * 2;     // fragment col pair
    int l0 = qt * 128 + warp * 16;

    // Q fragments (held all kernel), scaled, split hi/lo. kf = k16 index.
    uint32_t qh[2][4], ql[2][4];
    #pragma unroll
    for (int kf = 0; kf < 2; kf++) {
        #pragma unroll
        for (int half = 0; half < 2; half++) {
            int col = kf * 16 + half * 8 + cq;
            float2 v0 = *(const float2*)&Q[(size_t)(l0 + r) * 8192 + base + col];
            float2 v1 = *(const float2*)&Q[(size_t)(l0 + r + 8) * 8192 + base + col];
            v0.x *= SCALE; v0.y *= SCALE; v1.x *= SCALE; v1.y *= SCALE;
            pack_split(v0.x, v0.y, &qh[kf][half * 2 + 0], &ql[kf][half * 2 + 0]);
            pack_split(v1.x, v1.y, &qh[kf][half * 2 + 1], &ql[kf][half * 2 + 1]);
        }
    }
    // A-frag register order is (r,klo),(r+8,klo),(r,khi),(r+8,khi):
    // half0 wrote idx 0,1 (klo rows r,r+8); half1 wrote idx 2,3 (khi). OK.

    float o[4][4];
    #pragma unroll
    for (int nf = 0; nf < 4; nf++)
        #pragma unroll
        for (int e = 0; e < 4; e++) o[nf][e] = 0.f;
    float mrow0 = -1e30f, mrow1 = -1e30f, lrow0 = 0.f, lrow1 = 0.f;

    const float4* K4 = (const float4*)K;
    const float4* V4 = (const float4*)V;
    int srow = tid >> 2;          // 0..63 staging row
    int sc4  = tid & 3;           // float4 col group

    for (int kt = 0; kt < 8; kt++) {
        __syncthreads();
        // Stage K,V tile [64 x 32] fp32 -> bf16 hi/lo (coalesced float4 loads)
        #pragma unroll
        for (int i = 0; i < 2; i++) {
            int c4 = sc4 + i * 4;
            size_t gidx = ((size_t)(kt * 64 + srow) * 8192 + base) / 4 + c4;
            float4 kv = K4[gidx];
            float4 vv = V4[gidx];
            split_store4(&Kh[srow * LDSR + c4 * 4], &Kl[srow * LDSR + c4 * 4], kv);
            split_store4(&Vh[srow * LDSR + c4 * 4], &Vl[srow * LDSR + c4 * 4], vv);
        }
        __syncthreads();

        // S = Q K^T  (128x64 per block; this warp: 16x64 -> 8 n-frags)
        float s[8][4];
        #pragma unroll
        for (int nf = 0; nf < 8; nf++) {
            s[nf][0] = s[nf][1] = s[nf][2] = s[nf][3] = 0.f;
            #pragma unroll
            for (int kf = 0; kf < 2; kf++) {
                const __nv_bfloat16* pk = &Kh[(nf * 8 + (al16 & 7)) * LDSR + (al16 >> 3) * 8 + kf * 16];
                const __nv_bfloat16* pl = &Kl[(nf * 8 + (al16 & 7)) * LDSR + (al16 >> 3) * 8 + kf * 16];
                uint32_t bh[2], bl[2];
                ldsm_x2(bh, pk);
                ldsm_x2(bl, pl);
                mma_bf16(s[nf], qh[kf], bh);
                mma_bf16(s[nf], qh[kf], bl);
                mma_bf16(s[nf], ql[kf], bh);
            }
        }

        // Online softmax: rows r (c0,c1) and r+8 (c2,c3)
        float t0 = -1e30f, t1 = -1e30f;
        #pragma unroll
        for (int nf = 0; nf < 8; nf++) {
            t0 = fmaxf(t0, fmaxf(s[nf][0], s[nf][1]));
            t1 = fmaxf(t1, fmaxf(s[nf][2], s[nf][3]));
        }
        t0 = fmaxf(t0, __shfl_xor_sync(0xffffffffu, t0, 1));
        t0 = fmaxf(t0, __shfl_xor_sync(0xffffffffu, t0, 2));
        t1 = fmaxf(t1, __shfl_xor_sync(0xffffffffu, t1, 1));
        t1 = fmaxf(t1, __shfl_xor_sync(0xffffffffu, t1, 2));
        float mn0 = fmaxf(mrow0, t0), mn1 = fmaxf(mrow1, t1);
        float corr0 = __expf(mrow0 - mn0), corr1 = __expf(mrow1 - mn1);

        float rs0 = 0.f, rs1 = 0.f;
        #pragma unroll
        for (int nf = 0; nf < 8; nf++) {
            s[nf][0] = __expf(s[nf][0] - mn0); rs0 += s[nf][0];
            s[nf][1] = __expf(s[nf][1] - mn0); rs0 += s[nf][1];
            s[nf][2] = __expf(s[nf][2] - mn1); rs1 += s[nf][2];
            s[nf][3] = __expf(s[nf][3] - mn1); rs1 += s[nf][3];
        }
        rs0 += __shfl_xor_sync(0xffffffffu, rs0, 1);
        rs0 += __shfl_xor_sync(0xffffffffu, rs0, 2);
        rs1 += __shfl_xor_sync(0xffffffffu, rs1, 1);
        rs1 += __shfl_xor_sync(0xffffffffu, rs1, 2);
        lrow0 = lrow0 * corr0 + rs0;
        lrow1 = lrow1 * corr1 + rs1;
        mrow0 = mn0; mrow1 = mn1;

        #pragma unroll
        for (int nf = 0; nf < 4; nf++) {
            o[nf][0] *= corr0; o[nf][1] *= corr0;
            o[nf][2] *= corr1; o[nf][3] *= corr1;
        }

        // PV: P (from S frags, no shuffles) x V (ldmatrix.trans B-frags)
        #pragma unroll
        for (int kg = 0; kg < 4; kg++) {
            uint32_t ph[4], pl2[4];
            pack_split(s[2 * kg][0],     s[2 * kg][1],     &ph[0], &pl2[0]);
            pack_split(s[2 * kg][2],     s[2 * kg][3],     &ph[1], &pl2[1]);
            pack_split(s[2 * kg + 1][0], s[2 * kg + 1][1], &ph[2], &pl2[2]);
            pack_split(s[2 * kg + 1][2], s[2 * kg + 1][3], &ph[3], &pl2[3]);
            #pragma unroll
            for (int nf = 0; nf < 4; nf++) {
                const __nv_bfloat16* pvh = &Vh[(kg * 16 + al16) * LDSR + nf * 8];
                const __nv_bfloat16* pvl = &Vl[(kg * 16 + al16) * LDSR + nf * 8];
                uint32_t vbh[2], vbl[2];
                ldsm_x2_trans(vbh, pvh);
                ldsm_x2_trans(vbl, pvl);
                mma_bf16(o[nf], ph, vbh);
                mma_bf16(o[nf], ph, vbl);
                mma_bf16(o[nf], pl2, vbh);
            }
        }
    }

    float inv0 = 1.f / lrow0, inv1 = 1.f / lrow1;
    #pragma unroll
    for (int nf = 0; nf < 4; nf++) {
        int col = nf * 8 + cq;
        float2 o0 = make_float2(o[nf][0] * inv0, o[nf][1] * inv0);
        float2 o1 = make_float2(o[nf][2] * inv1, o[nf][3] * inv1);
        *(float2*)&O[(size_t)(l0 + r) * 8192 + base + col]     = o0;
        *(float2*)&O[(size_t)(l0 + r + 8) * 8192 + base + col] = o1;
    }
}

// ---------------------------------------------------------------------------
// Scatter: short token layout -> output [n,c,t,h,w]
// grid (16, 64, 4) block (32, 8)
// ---------------------------------------------------------------------------
__global__ void scatter_out(const float* __restrict__ src, float* __restrict__ out) {
    int ct = blockIdx.x >> 1, xt = blockIdx.x & 1;
    int y  = blockIdx.y;
    int nn = blockIdx.z >> 1, t = blockIdx.z & 1;
    int c0 = ct * 32, x0 = xt * 32;
    int bh = y >> 4, ih = y & 15;
    __shared__ float sm[32][33];
    int tx = threadIdx.x, ty = threadIdx.y;
    #pragma unroll
    for (int i = 0; i < 4; i++) {
        int xi = ty + i * 8;
        int x = x0 + xi;
        int bw = x >> 4, iw = x & 15;
        int s  = t * 256 + ih * 16 + iw;
        int b2 = nn * 16 + bh * 4 + bw;
        int token2 = s * 32 + b2;
        sm[tx][xi] = src[(size_t)token2 * CDIM + c0 + tx];
    }
    __syncthreads();
    #pragma unroll
    for (int i = 0; i < 4; i++) {
        int ci = ty + i * 8;
        out[((size_t)(nn * CDIM + c0 + ci) * 2 + t) * 4096 + (size_t)y * 64 + x0 + tx] = sm[ci][tx];
    }
}

// ---------------------------------------------------------------------------
extern "C" void kernel_launch(void* const* d_in, const int* in_sizes, int n_in,
                              void* d_out, int out_size) {
    (void)in_sizes; (void)n_in; (void)out_size;
    const float* q      = (const float*)d_in[0];
    const float* k      = (const float*)d_in[1];
    const float* v      = (const float*)d_in[2];
    const float* pos    = (const float*)d_in[3];
    const float* wl_in  = (const float*)d_in[4];
    const float* bl_in  = (const float*)d_in[5];
    const float* wl_out = (const float*)d_in[6];
    const float* bl_out = (const float*)d_in[7];
    const float* ws_in  = (const float*)d_in[8];
    const float* bs_in  = (const float*)d_in[9];
    const float* ws_out = (const float*)d_in[10];
    const float* bs_out = (const float*)d_in[11];
    float* out = (float*)d_out;

    float *px0, *px1, *px2, *pq, *pk, *pv, *po, *pm;
    cudaGetSymbolAddress((void**)&px0, g_x0);
    cudaGetSymbolAddress((void**)&px1, g_x1);
    cudaGetSymbolAddress((void**)&px2, g_x2);
    cudaGetSymbolAddress((void**)&pq,  g_qb);
    cudaGetSymbolAddress((void**)&pk,  g_kb);
    cudaGetSymbolAddress((void**)&pv,  g_vb);
    cudaGetSymbolAddress((void**)&po,  g_ob);
    cudaGetSymbolAddress((void**)&pm,  g_mb);

    dim3 gGather(16, 64, 4), bGather(32, 8);
    dim3 gGemm(4, 128);
    dim3 gAttn1(512, 8);
    dim3 gAttn2(4, 8, 32);

    // Phase 1: gather to long layout (+pos)
    gather_long<<<gGather, bGather>>>(q, k, v, pos);

    // Phase 2: MHA1 input projections
    gemm_nt_tc<<<gGemm, 256>>>(px0, wl_in,              bl_in,       pq);
    gemm_nt_tc<<<gGemm, 256>>>(px1, wl_in + 256 * 256,  bl_in + 256, pk);
    gemm_nt_tc<<<gGemm, 256>>>(px2, wl_in + 512 * 256,  bl_in + 512, pv);

    // Phase 3: long attention
    attn1<<<gAttn1, 32>>>(pq, pk, pv, po);

    // Phase 4: MHA1 output projection
    gemm_nt_tc<<<gGemm, 256>>>(po, wl_out, bl_out, pm);

    // Phase 5: permute long -> short, add pos
    reindex_short<<<TOK, 256>>>();

    // Phase 6: MHA2 input projections (query and key share input g_x0)
    gemm_nt_tc<<<gGemm, 256>>>(px0, ws_in,              bs_in,       pq);
    gemm_nt_tc<<<gGemm, 256>>>(px0, ws_in + 256 * 256,  bs_in + 256, pk);
    gemm_nt_tc<<<gGemm, 256>>>(px2, ws_in + 512 * 256,  bs_in + 512, pv);

    // Phase 7: short attention (tensor-core flash)
    attn2_tc<<<gAttn2, 256>>>(pq, pk, pv, po);

    // Phase 8: MHA2 output projection + scatter to output layout
    gemm_nt_tc<<<gGemm, 256>>>(po, ws_out, bs_out, pm);
    scatter_out<<<gGather, bGather>>>(pm, out);
}